// round 6
// baseline (speedup 1.0000x reference)
#include <cuda_runtime.h>
#include <cstdint>

#define B_  32
#define L_  1024
#define D_  1024
#define T_  10
#define M_  (B_*L_)
#define NC  32
#define CHUNK 16
#define S_  64
#define RPB 631            // 1 + 63*10
#define NREC (B_*RPB)      // 20192

#define LOG2E 1.4426950408889634f
#define LN2   0.6931471805599453f

// ---------------- device scratch ----------------
__device__ uint32_t g_Wb[32*512];      // weights bf16x2 packed [c][d/2]
__device__ float g_Z[(size_t)M_*NC];
__device__ float g_em2[(size_t)M_*T_];
__device__ float g_T2[T_*T_];
__device__ float g_P [T_*T_];
__device__ float g_s2[T_];
__device__ float g_e2[T_];
__device__ float g_Mbuf[(size_t)NREC*T_];
__device__ float g_part[B_];

__device__ __forceinline__ float ex2f_(float x){ float r; asm("ex2.approx.f32 %0, %1;" : "=f"(r) : "f"(x)); return r; }
__device__ __forceinline__ float lg2f_(float x){ float r; asm("lg2.approx.f32 %0, %1;" : "=f"(r) : "f"(x)); return r; }

// pack two f32 -> bf16x2, 'lo' in low 16 bits
#define CVT2BF(res, lo, hi) asm("cvt.rn.bf16x2.f32 %0, %1, %2;" : "=r"(res) : "f"(hi), "f"(lo))

__device__ __forceinline__ uint32_t smem_u32(const void* p){
    uint32_t a; asm("{ .reg .u64 t; cvta.to.shared.u64 t, %1; cvt.u32.u64 %0, t; }" : "=r"(a) : "l"(p)); return a;
}
__device__ __forceinline__ void cp16(uint32_t dst, const void* src){
    asm volatile("cp.async.cg.shared.global [%0], [%1], 16;" :: "r"(dst), "l"(src) : "memory");
}
#define CP_COMMIT() asm volatile("cp.async.commit_group;" ::: "memory")
#define CP_WAIT(n)  asm volatile("cp.async.wait_group %0;" :: "n"(n) : "memory")

__device__ __forceinline__ void mma16816(float c[4], uint32_t a0, uint32_t a1, uint32_t a2, uint32_t a3,
                                         uint32_t b0, uint32_t b1){
    asm volatile("mma.sync.aligned.m16n8k16.row.col.f32.bf16.bf16.f32 "
                 "{%0,%1,%2,%3}, {%4,%5,%6,%7}, {%8,%9}, {%0,%1,%2,%3};"
                 : "+f"(c[0]), "+f"(c[1]), "+f"(c[2]), "+f"(c[3])
                 : "r"(a0), "r"(a1), "r"(a2), "r"(a3), "r"(b0), "r"(b1));
}

// ---------------- K1: setup ----------------
__global__ void k1_setup(const float* __restrict__ conv_w,
                         const float* __restrict__ start_t,
                         const float* __restrict__ end_t,
                         const float* __restrict__ trans)
{
    int tid = blockIdx.x*blockDim.x + threadIdx.x;
    for (int u = tid; u < 32*512; u += gridDim.x*blockDim.x){
        int c = u >> 9, j = u & 511;
        float lo = 0.f, hi = 0.f;
        if (c < 30){
            int t = c/3, kk = c - 3*t;
            lo = conv_w[(t*D_ + 2*j  )*3 + kk];
            hi = conv_w[(t*D_ + 2*j+1)*3 + kk];
        }
        uint32_t p; CVT2BF(p, lo, hi);
        g_Wb[u] = p;
    }
    if (tid < T_*T_){ float tv = trans[tid]*LOG2E; g_T2[tid] = tv; g_P[tid] = ex2f_(tv); }
    if (tid < T_){ g_s2[tid] = start_t[tid]*LOG2E; g_e2[tid] = end_t[tid]*LOG2E; }
}

// ---------------- K2: bf16 HMMA GEMM, cp.async-staged A ----------------
// Z[m][c] = X[m,:].W[c,:]. M=32768, N=32, K=1024.
// CTA: 256 thr / 8 warps, 128-row tile. K in 16 chunks of 64 fp32.
// A smem: fp32, row stride 72 words (rows conflict-free for LDS.64 frag reads),
// 3-stage ring. B smem: bf16x2 words, [32 c][516 words].
#define ARS   72                 // A row stride (words)
#define ABUF  (128*ARS)          // words per A stage = 9216
#define SWS   516                // B row stride (words)
#define AW_TOT (3*ABUF)          // 27648 words
#define SMEM_K2_BYTES ((AW_TOT + 32*SWS)*4)   // 110592 + 66048 = 176640

__global__ void __launch_bounds__(256) k2_mma(const float* __restrict__ X)
{
    extern __shared__ uint32_t smw[];
    uint32_t* sA = smw;                 // fp32 words
    uint32_t* sW = smw + AW_TOT;        // bf16x2 words
    const uint32_t sA_u = smem_u32(sA);
    const int tid = threadIdx.x, wid = tid >> 5, lane = tid & 31;
    const int g  = lane >> 2;
    const int tg = lane & 3;
    const int rowBase = blockIdx.x*128;

    // cp.async lane mapping for A: per warp, 8 instr j: 4 rows x 128B, fully coalesced
    const int a_sub = lane >> 3;        // 0..3 (row within group of 4)
    const int a_wq  = lane & 7;         // 0..7 (16B column within 128B half-row)

    // issue A chunks 0,1,2
#pragma unroll
    for (int pre = 0; pre < 3; pre++){
#pragma unroll
        for (int j = 0; j < 8; j++){
            int rg = j & 3, half = j >> 2;
            int row = wid*16 + rg*4 + a_sub;
            uint32_t dst = sA_u + (uint32_t)((pre*ABUF + row*ARS + half*32 + a_wq*4)*4);
            const float* src = X + (size_t)(rowBase + row)*D_ + pre*64 + half*32 + a_wq*4;
            cp16(dst, src);
        }
        CP_COMMIT();
    }

    // load B (64KB) into smem
    for (int idx = tid; idx < 32*512/4; idx += 256){
        int c = idx >> 7, jq = idx & 127;      // 128 uint4 per row
        uint4 v = *reinterpret_cast<const uint4*>(&g_Wb[c*512 + jq*4]);
        *reinterpret_cast<uint4*>(&sW[c*SWS + jq*4]) = v;
    }

    float acc[4][4];
#pragma unroll
    for (int n = 0; n < 4; n++)
#pragma unroll
        for (int q = 0; q < 4; q++) acc[n][q] = 0.f;

    __syncthreads();   // B ready (A chunk readiness via CP_WAIT below)

#pragma unroll 1
    for (int i = 0; i < 16; i++){
        if (i < 14)      { CP_WAIT(2); }
        else if (i == 14){ CP_WAIT(1); }
        else             { CP_WAIT(0); }
        __syncthreads();

        const uint32_t* abuf = sA + (i % 3)*ABUF;
        const int arow = (wid*16 + g)*ARS;
#pragma unroll
        for (int q = 0; q < 4; q++){
            // A fragments: LDS.64 fp32 pairs -> cvt bf16x2
            float2 f0 = *reinterpret_cast<const float2*>(abuf + arow + q*16 + 2*tg);
            float2 f1 = *reinterpret_cast<const float2*>(abuf + arow + 8*ARS + q*16 + 2*tg);
            float2 f2 = *reinterpret_cast<const float2*>(abuf + arow + q*16 + 8 + 2*tg);
            float2 f3 = *reinterpret_cast<const float2*>(abuf + arow + 8*ARS + q*16 + 8 + 2*tg);
            uint32_t a0,a1,a2,a3;
            CVT2BF(a0, f0.x, f0.y);
            CVT2BF(a1, f1.x, f1.y);
            CVT2BF(a2, f2.x, f2.y);
            CVT2BF(a3, f3.x, f3.y);
            const int bw = i*32 + q*8 + tg;
#pragma unroll
            for (int n = 0; n < 4; n++){
                const uint32_t* wr = &sW[(n*8 + g)*SWS];
                mma16816(acc[n], a0,a1,a2,a3, wr[bw], wr[bw+4]);
            }
        }
        __syncthreads();   // all warps done with buffer before refill

        if (i + 3 < 16){
            int ci = i + 3;
#pragma unroll
            for (int j = 0; j < 8; j++){
                int rg = j & 3, half = j >> 2;
                int row = wid*16 + rg*4 + a_sub;
                uint32_t dst = sA_u + (uint32_t)(((ci%3)*ABUF + row*ARS + half*32 + a_wq*4)*4);
                const float* src = X + (size_t)(rowBase + row)*D_ + ci*64 + half*32 + a_wq*4;
                cp16(dst, src);
            }
            CP_COMMIT();
        }
    }

    const int row0 = rowBase + wid*16 + g;
    float* z0 = &g_Z[(size_t)row0*NC + 2*tg];
    float* z8 = z0 + 8*NC;
#pragma unroll
    for (int n = 0; n < 4; n++){
        *reinterpret_cast<float2*>(z0 + n*8) = make_float2(acc[n][0], acc[n][1]);
        *reinterpret_cast<float2*>(z8 + n*8) = make_float2(acc[n][2], acc[n][3]);
    }
}

// ---------------- K3: shifted gather -> em2 ----------------
__global__ void k3_gather(const float* __restrict__ conv_b)
{
    int idx = blockIdx.x*blockDim.x + threadIdx.x;
    if (idx >= M_*T_) return;
    int m = idx / T_, t = idx - m*T_;
    int l = m & (L_-1);
    float v = g_Z[(size_t)m*NC + t*3 + 1] + conv_b[t];
    if (l > 0)     v += g_Z[(size_t)(m-1)*NC + t*3 + 0];
    if (l < L_-1)  v += g_Z[(size_t)(m+1)*NC + t*3 + 2];
    g_em2[idx] = v * LOG2E;
}

// ---------------- K4: chunked CRF recursions ----------------
__global__ void __launch_bounds__(128) k4_chunks(const int* __restrict__ mask)
{
    int gtid = blockIdx.x*blockDim.x + threadIdx.x;
    int w   = gtid >> 5;
    int lid = gtid & 31;
    int g = lid/10; if (g > 2) g = 2;
    int j = lid - g*10;
    int jc = (j < 10) ? j : 9;
    int rid = w*3 + g;
    bool valid = (rid < NREC) && (j < 10);
    if (rid >= NREC) rid = NREC-1;

    int b   = rid / RPB;
    int rem = rid - b*RPB;
    int s, irow;
    if (rem == 0){ s = 0; irow = 0; }
    else { s = 1 + (rem-1)/10; irow = (rem-1) - ((rem-1)/10)*10; }

    float Pv[10];
#pragma unroll
    for (int k=0;k<10;k++) Pv[k] = g_P[k*10 + jc];

    const float* emB = &g_em2[(size_t)b*L_*T_];
    const int*   mrow = mask + b*L_;

    float a[10], aj;
    if (s == 0){
#pragma unroll
        for (int k=0;k<10;k++) a[k] = g_s2[k] + emB[k];
        aj = g_s2[jc] + emB[jc];
    } else {
#pragma unroll
        for (int k=0;k<10;k++) a[k] = (k==irow) ? 0.f : -1e30f;
        aj = (jc==irow) ? 0.f : -1e30f;
    }

    int lbase = s*CHUNK;
#pragma unroll 1
    for (int it=0; it<CHUNK; it++){
        int l = lbase + it;
        float e  = emB[l*T_ + jc];
        int   mk = mrow[l];

        float mx = a[0];
#pragma unroll
        for (int k=1;k<10;k++) mx = fmaxf(mx, a[k]);

        float sum = 0.f;
#pragma unroll
        for (int k=0;k<10;k++) sum += ex2f_(a[k]-mx) * Pv[k];

        float anew = lg2f_(sum) + mx + e;
        bool skip = (s==0) && (it==0);
        if (mk && !skip) aj = anew;
#pragma unroll
        for (int k=0;k<10;k++) a[k] = __shfl_sync(0xffffffffu, aj, g*10+k);
    }
    if (valid) g_Mbuf[(size_t)rid*T_ + j] = aj;
}

// ---------------- K5: combine + numerator ----------------
__global__ void k5_combine(const int* __restrict__ mask, const int* __restrict__ labels)
{
    int b   = blockIdx.x;
    int lid = threadIdx.x;
    bool act = lid < 10;
    int jc = act ? lid : 9;

    const float* mbB = &g_Mbuf[(size_t)b*RPB*T_];
    float a[10];
#pragma unroll
    for (int k=0;k<10;k++) a[k] = mbB[k];

    float nxt[10];
#pragma unroll
    for (int i=0;i<10;i++) nxt[i] = mbB[(1 + i)*T_ + jc];

    float vj = a[0];
    for (int s=1; s<S_; s++){
        float cur[10];
#pragma unroll
        for (int i=0;i<10;i++) cur[i] = nxt[i];
        if (s+1 < S_){
#pragma unroll
            for (int i=0;i<10;i++) nxt[i] = mbB[(1 + s*10 + i)*T_ + jc];
        }
        float t[10];
        float mx = -1e30f;
#pragma unroll
        for (int i=0;i<10;i++){
            t[i] = a[i] + cur[i];
            mx = fmaxf(mx, t[i]);
        }
        float sum = 0.f;
#pragma unroll
        for (int i=0;i<10;i++) sum += ex2f_(t[i]-mx);
        vj = lg2f_(sum) + mx;
#pragma unroll
        for (int k=0;k<10;k++) a[k] = __shfl_sync(0xffffffffu, vj, k);
    }
    float v = act ? (vj + g_e2[jc]) : -1e30f;
    float mx = v;
    for (int off=16; off>0; off>>=1) mx = fmaxf(mx, __shfl_xor_sync(0xffffffffu, mx, off));
    float p = act ? ex2f_(v - mx) : 0.f;
    for (int off=16; off>0; off>>=1) p += __shfl_xor_sync(0xffffffffu, p, off);
    float denom2 = lg2f_(p) + mx;

    const int* lb = labels + b*L_;
    const int* mb = mask   + b*L_;
    const float* emB = &g_em2[(size_t)b*L_*T_];
    float nacc = 0.f; int slen = 0;
    for (int l=lid; l<L_; l+=32){
        int ml = mb[l]; slen += ml;
        if (l == 0) nacc += g_s2[lb[0]] + emB[lb[0]];
        else if (ml) nacc += g_T2[lb[l-1]*10 + lb[l]] + emB[l*T_ + lb[l]];
    }
    for (int off=16; off>0; off>>=1){
        nacc += __shfl_xor_sync(0xffffffffu, nacc, off);
        slen += __shfl_xor_sync(0xffffffffu, slen, off);
    }
    float num2 = nacc + g_e2[lb[slen-1]];
    if (lid == 0) g_part[b] = (denom2 - num2) * LN2;
}

// ---------------- K6: final reduce ----------------
__global__ void k6_final(float* __restrict__ out)
{
    int lid = threadIdx.x;
    float v = g_part[lid];
    for (int off=16; off>0; off>>=1) v += __shfl_xor_sync(0xffffffffu, v, off);
    if (lid == 0) out[0] = v;
}

// ---------------- launch ----------------
extern "C" void kernel_launch(void* const* d_in, const int* in_sizes, int n_in,
                              void* d_out, int out_size)
{
    const float* emb     = (const float*)d_in[0];
    const int*   mask    = (const int*)  d_in[1];
    const int*   labels  = (const int*)  d_in[2];
    const float* conv_w  = (const float*)d_in[3];
    const float* conv_b  = (const float*)d_in[4];
    const float* start_t = (const float*)d_in[5];
    const float* end_t   = (const float*)d_in[6];
    const float* trans   = (const float*)d_in[7];

    static bool attr_done = false;
    if (!attr_done){
        cudaFuncSetAttribute(k2_mma, cudaFuncAttributeMaxDynamicSharedMemorySize, SMEM_K2_BYTES);
        attr_done = true;
    }

    k1_setup<<<64, 256>>>(conv_w, start_t, end_t, trans);
    k2_mma <<<M_/128, 256, SMEM_K2_BYTES>>>(emb);
    k3_gather<<<(M_*T_ + 255)/256, 256>>>(conv_b);
    int nwarp = (NREC + 2)/3;
    int nthr  = nwarp*32;
    k4_chunks<<<(nthr + 127)/128, 128>>>(mask);
    k5_combine<<<B_, 32>>>(mask, labels);
    k6_final<<<1, 32>>>((float*)d_out);
}

// round 7
// speedup vs baseline: 1.0313x; 1.0313x over previous
#include <cuda_runtime.h>
#include <cstdint>

#define B_  32
#define L_  1024
#define D_  1024
#define T_  10
#define M_  (B_*L_)
#define NC  32
#define CHUNK 32
#define S_  32
#define RPB 311            // 1 + 31*10
#define NREC (B_*RPB)      // 9952

#define LOG2E 1.4426950408889634f
#define LN2   0.6931471805599453f

// ---------------- device scratch ----------------
__device__ uint32_t g_Wb[32*512];      // weights bf16x2 packed [c][d/2]
__device__ float g_em2[(size_t)M_*T_];
__device__ float g_T2[T_*T_];
__device__ float g_P [T_*T_];
__device__ float g_s2[T_];
__device__ float g_e2[T_];
__device__ float g_Mbuf[(size_t)NREC*T_];

__device__ __forceinline__ float ex2f_(float x){ float r; asm("ex2.approx.f32 %0, %1;" : "=f"(r) : "f"(x)); return r; }
__device__ __forceinline__ float lg2f_(float x){ float r; asm("lg2.approx.f32 %0, %1;" : "=f"(r) : "f"(x)); return r; }

// pack two f32 -> bf16x2, 'lo' in low 16 bits
#define CVT2BF(res, lo, hi) asm("cvt.rn.bf16x2.f32 %0, %1, %2;" : "=r"(res) : "f"(hi), "f"(lo))

__device__ __forceinline__ void mma16816(float c[4], uint32_t a0, uint32_t a1, uint32_t a2, uint32_t a3,
                                         uint32_t b0, uint32_t b1){
    asm volatile("mma.sync.aligned.m16n8k16.row.col.f32.bf16.bf16.f32 "
                 "{%0,%1,%2,%3}, {%4,%5,%6,%7}, {%8,%9}, {%0,%1,%2,%3};"
                 : "+f"(c[0]), "+f"(c[1]), "+f"(c[2]), "+f"(c[3])
                 : "r"(a0), "r"(a1), "r"(a2), "r"(a3), "r"(b0), "r"(b1));
}

// ---------------- K1: setup ----------------
__global__ void k1_setup(const float* __restrict__ conv_w,
                         const float* __restrict__ start_t,
                         const float* __restrict__ end_t,
                         const float* __restrict__ trans)
{
    int tid = blockIdx.x*blockDim.x + threadIdx.x;
    for (int u = tid; u < 32*512; u += gridDim.x*blockDim.x){
        int c = u >> 9, j = u & 511;
        float lo = 0.f, hi = 0.f;
        if (c < 30){
            int t = c/3, kk = c - 3*t;
            lo = conv_w[(t*D_ + 2*j  )*3 + kk];
            hi = conv_w[(t*D_ + 2*j+1)*3 + kk];
        }
        uint32_t p; CVT2BF(p, lo, hi);
        g_Wb[u] = p;
    }
    if (tid < T_*T_){ float tv = trans[tid]*LOG2E; g_T2[tid] = tv; g_P[tid] = ex2f_(tv); }
    if (tid < T_){ g_s2[tid] = start_t[tid]*LOG2E; g_e2[tid] = end_t[tid]*LOG2E; }
}

// ---------------- K2: fused bf16 HMMA GEMM + conv gather -> em2 ----------------
// CTA: 256 thr / 8 warps, 128-row tile. Warp = 16 rows x 32 cols.
// Epilogue: acc -> smem Z window (4 passes of 32 rows), em2 written directly.
// Boundary rows (rowBase-1, rowBase+128) computed scalar from bf16 inputs.
#define SWS    516                  // B row stride (words)
#define ZTS    33                   // Z tile row stride (words)
#define ZROWS  34                   // window rows per pass
#define SMEM_WORDS (32*SWS + ZROWS*ZTS + 64)
#define SMEM_K2_BYTES (SMEM_WORDS*4)

__global__ void __launch_bounds__(256) k2_fused(const float* __restrict__ X,
                                                const float* __restrict__ conv_b)
{
    extern __shared__ uint32_t smw[];
    uint32_t* sW = smw;                       // 32*SWS words
    float*    sZ = (float*)(smw + 32*SWS);    // ZROWS*ZTS floats
    float*    sZb = (float*)(smw + 32*SWS + ZROWS*ZTS);  // [2][32]

    const int tid = threadIdx.x, wid = tid >> 5, lane = tid & 31;
    const int g  = lane >> 2;
    const int tg = lane & 3;
    const int rowBase = blockIdx.x*128;

    // ---- boundary rows: scalar bf16 dot products (rows rowBase-1, rowBase+128)
    {
        const int pair = tid >> 2, sub = tid & 3;
        const int prow = pair >> 5, c = pair & 31;
        const int loValid = (rowBase & 1023) != 0;
        const int hiValid = ((rowBase + 128) & 1023) != 0;
        const int valid = prow ? hiValid : loValid;
        float part = 0.f;
        if (valid){
            const float* xb = X + (size_t)(prow ? rowBase + 128 : rowBase - 1)*D_;
            const uint32_t* wr = &g_Wb[c*512];
#pragma unroll 4
            for (int i4 = 0; i4 < 64; i4++){
                int k = sub*256 + i4*4;
                float4 xv = *reinterpret_cast<const float4*>(xb + k);
                uint32_t xp0, xp1;
                CVT2BF(xp0, xv.x, xv.y);
                CVT2BF(xp1, xv.z, xv.w);
                uint2 wv = *reinterpret_cast<const uint2*>(wr + (k >> 1));
                float x0 = __uint_as_float(xp0 << 16), x1 = __uint_as_float(xp0 & 0xffff0000u);
                float x2 = __uint_as_float(xp1 << 16), x3 = __uint_as_float(xp1 & 0xffff0000u);
                float w0 = __uint_as_float(wv.x << 16), w1 = __uint_as_float(wv.x & 0xffff0000u);
                float w2 = __uint_as_float(wv.y << 16), w3 = __uint_as_float(wv.y & 0xffff0000u);
                part += x0*w0 + x1*w1 + x2*w2 + x3*w3;
            }
        }
        part += __shfl_xor_sync(0xffffffffu, part, 1);
        part += __shfl_xor_sync(0xffffffffu, part, 2);
        if (sub == 0) sZb[prow*32 + c] = part;
    }

    // ---- load B (64KB) into smem
    for (int idx = tid; idx < 32*512/4; idx += 256){
        int c = idx >> 7, jq = idx & 127;
        uint4 v = *reinterpret_cast<const uint4*>(&g_Wb[c*512 + jq*4]);
        *reinterpret_cast<uint4*>(&sW[c*SWS + jq*4]) = v;
    }
    __syncthreads();

    // ---- main mma loop (R4 structure)
    const int row0 = rowBase + wid*16 + g;
    const float* xr0 = X + (size_t)row0 * D_ + 2*tg;
    const float* xr8 = xr0 + 8*D_;

    float acc[4][4];
#pragma unroll
    for (int n = 0; n < 4; n++)
#pragma unroll
        for (int q = 0; q < 4; q++) acc[n][q] = 0.f;

    const uint32_t* wb0 = &sW[(0*8 + g)*SWS + tg];
    const uint32_t* wb1 = &sW[(1*8 + g)*SWS + tg];
    const uint32_t* wb2 = &sW[(2*8 + g)*SWS + tg];
    const uint32_t* wb3 = &sW[(3*8 + g)*SWS + tg];

#pragma unroll 4
    for (int i = 0; i < 64; i++){
        const int k0 = i*16;
        float2 x0 = *reinterpret_cast<const float2*>(xr0 + k0);
        float2 x1 = *reinterpret_cast<const float2*>(xr8 + k0);
        float2 x2 = *reinterpret_cast<const float2*>(xr0 + k0 + 8);
        float2 x3 = *reinterpret_cast<const float2*>(xr8 + k0 + 8);
        uint32_t a0,a1,a2,a3;
        CVT2BF(a0, x0.x, x0.y);
        CVT2BF(a1, x1.x, x1.y);
        CVT2BF(a2, x2.x, x2.y);
        CVT2BF(a3, x3.x, x3.y);
        const int kh = i*8;
        mma16816(acc[0], a0,a1,a2,a3, wb0[kh], wb0[kh+4]);
        mma16816(acc[1], a0,a1,a2,a3, wb1[kh], wb1[kh+4]);
        mma16816(acc[2], a0,a1,a2,a3, wb2[kh], wb2[kh+4]);
        mma16816(acc[3], a0,a1,a2,a3, wb3[kh], wb3[kh+4]);
    }

    // ---- epilogue: 4 windowed passes of 32 em-rows each
    const int m1 = row0;        // rows owned by this thread's fragments
    const int m2 = row0 + 8;
    float cb[10];
#pragma unroll
    for (int t = 0; t < 10; t++) cb[t] = conv_b[t];

#pragma unroll 1
    for (int p = 0; p < 4; p++){
        const int base_p = rowBase + 32*p - 1;   // global row of sZ local 0
        __syncthreads();    // previous pass readers done before overwrite
        // store acc rows that fall in window [base_p, base_p+33]
        {
            int zr1 = m1 - base_p;
            if (zr1 >= 0 && zr1 <= 33){
#pragma unroll
                for (int n = 0; n < 4; n++){
                    sZ[zr1*ZTS + n*8 + 2*tg]     = acc[n][0];
                    sZ[zr1*ZTS + n*8 + 2*tg + 1] = acc[n][1];
                }
            }
            int zr2 = m2 - base_p;
            if (zr2 >= 0 && zr2 <= 33){
#pragma unroll
                for (int n = 0; n < 4; n++){
                    sZ[zr2*ZTS + n*8 + 2*tg]     = acc[n][2];
                    sZ[zr2*ZTS + n*8 + 2*tg + 1] = acc[n][3];
                }
            }
            if (p == 0 && tid < 32) sZ[0*ZTS + tid]  = sZb[tid];        // row rowBase-1
            if (p == 3 && tid < 32) sZ[33*ZTS + tid] = sZb[32 + tid];   // row rowBase+128
        }
        __syncthreads();
        // compute em for rows base_p+1 .. base_p+32 (32 rows x 10 tags)
        for (int idx = tid; idx < 320; idx += 256){
            int r = idx / 10, t = idx - r*10;
            int m = base_p + 1 + r;
            int l = m & (L_-1);
            int zr = r + 1;
            float v = sZ[zr*ZTS + 3*t + 1] + cb[t];
            if (l > 0)      v += sZ[(zr-1)*ZTS + 3*t];
            if (l < L_-1)   v += sZ[(zr+1)*ZTS + 3*t + 2];
            g_em2[(size_t)m*T_ + t] = v * LOG2E;
        }
    }
}

// ---------------- K4: chunked CRF recursions ----------------
__global__ void __launch_bounds__(128) k4_chunks(const int* __restrict__ mask)
{
    int gtid = blockIdx.x*blockDim.x + threadIdx.x;
    int w   = gtid >> 5;
    int lid = gtid & 31;
    int g = lid/10; if (g > 2) g = 2;
    int j = lid - g*10;
    int jc = (j < 10) ? j : 9;
    int rid = w*3 + g;
    bool valid = (rid < NREC) && (j < 10);
    if (rid >= NREC) rid = NREC-1;

    int b   = rid / RPB;
    int rem = rid - b*RPB;
    int s, irow;
    if (rem == 0){ s = 0; irow = 0; }
    else { s = 1 + (rem-1)/10; irow = (rem-1) - ((rem-1)/10)*10; }

    float Pv[10];
#pragma unroll
    for (int k=0;k<10;k++) Pv[k] = g_P[k*10 + jc];

    const float* emB = &g_em2[(size_t)b*L_*T_];
    const int*   mrow = mask + b*L_;

    float a[10], aj;
    if (s == 0){
#pragma unroll
        for (int k=0;k<10;k++) a[k] = g_s2[k] + emB[k];
        aj = g_s2[jc] + emB[jc];
    } else {
#pragma unroll
        for (int k=0;k<10;k++) a[k] = (k==irow) ? 0.f : -1e30f;
        aj = (jc==irow) ? 0.f : -1e30f;
    }

    int lbase = s*CHUNK;
#pragma unroll 1
    for (int it=0; it<CHUNK; it++){
        int l = lbase + it;
        float e  = emB[l*T_ + jc];
        int   mk = mrow[l];

        float mx = a[0];
#pragma unroll
        for (int k=1;k<10;k++) mx = fmaxf(mx, a[k]);

        float sum = 0.f;
#pragma unroll
        for (int k=0;k<10;k++) sum += ex2f_(a[k]-mx) * Pv[k];

        float anew = lg2f_(sum) + mx + e;
        bool skip = (s==0) && (it==0);
        if (mk && !skip) aj = anew;
#pragma unroll
        for (int k=0;k<10;k++) a[k] = __shfl_sync(0xffffffffu, aj, g*10+k);
    }
    if (valid) g_Mbuf[(size_t)rid*T_ + j] = aj;
}

// ---------------- K5: combine + numerator + final reduce (1 block) ----------
__global__ void __launch_bounds__(1024) k5_combine(const int* __restrict__ mask,
                                                   const int* __restrict__ labels,
                                                   float* __restrict__ out)
{
    __shared__ float sp[32];
    int b   = threadIdx.x >> 5;
    int lid = threadIdx.x & 31;
    bool act = lid < 10;
    int jc = act ? lid : 9;

    const float* mbB = &g_Mbuf[(size_t)b*RPB*T_];
    float a[10];
#pragma unroll
    for (int k=0;k<10;k++) a[k] = mbB[k];

    float nxt[10];
#pragma unroll
    for (int i=0;i<10;i++) nxt[i] = mbB[(1 + i)*T_ + jc];

    float vj = a[0];
    for (int s=1; s<S_; s++){
        float cur[10];
#pragma unroll
        for (int i=0;i<10;i++) cur[i] = nxt[i];
        if (s+1 < S_){
#pragma unroll
            for (int i=0;i<10;i++) nxt[i] = mbB[(1 + s*10 + i)*T_ + jc];
        }
        float t[10];
        float mx = -1e30f;
#pragma unroll
        for (int i=0;i<10;i++){
            t[i] = a[i] + cur[i];
            mx = fmaxf(mx, t[i]);
        }
        float sum = 0.f;
#pragma unroll
        for (int i=0;i<10;i++) sum += ex2f_(t[i]-mx);
        vj = lg2f_(sum) + mx;
#pragma unroll
        for (int k=0;k<10;k++) a[k] = __shfl_sync(0xffffffffu, vj, k);
    }
    float v = act ? (vj + g_e2[jc]) : -1e30f;
    float mx = v;
    for (int off=16; off>0; off>>=1) mx = fmaxf(mx, __shfl_xor_sync(0xffffffffu, mx, off));
    float p = act ? ex2f_(v - mx) : 0.f;
    for (int off=16; off>0; off>>=1) p += __shfl_xor_sync(0xffffffffu, p, off);
    float denom2 = lg2f_(p) + mx;

    const int* lb = labels + b*L_;
    const int* mb = mask   + b*L_;
    const float* emB = &g_em2[(size_t)b*L_*T_];
    float nacc = 0.f; int slen = 0;
    for (int l=lid; l<L_; l+=32){
        int ml = mb[l]; slen += ml;
        if (l == 0) nacc += g_s2[lb[0]] + emB[lb[0]];
        else if (ml) nacc += g_T2[lb[l-1]*10 + lb[l]] + emB[l*T_ + lb[l]];
    }
    for (int off=16; off>0; off>>=1){
        nacc += __shfl_xor_sync(0xffffffffu, nacc, off);
        slen += __shfl_xor_sync(0xffffffffu, slen, off);
    }
    float num2 = nacc + g_e2[lb[slen-1]];
    if (lid == 0) sp[b] = (denom2 - num2) * LN2;

    __syncthreads();
    if (threadIdx.x < 32){
        float vv = sp[threadIdx.x];
        for (int off=16; off>0; off>>=1) vv += __shfl_xor_sync(0xffffffffu, vv, off);
        if (threadIdx.x == 0) out[0] = vv;
    }
}

// ---------------- launch ----------------
extern "C" void kernel_launch(void* const* d_in, const int* in_sizes, int n_in,
                              void* d_out, int out_size)
{
    const float* emb     = (const float*)d_in[0];
    const int*   mask    = (const int*)  d_in[1];
    const int*   labels  = (const int*)  d_in[2];
    const float* conv_w  = (const float*)d_in[3];
    const float* conv_b  = (const float*)d_in[4];
    const float* start_t = (const float*)d_in[5];
    const float* end_t   = (const float*)d_in[6];
    const float* trans   = (const float*)d_in[7];

    static bool attr_done = false;
    if (!attr_done){
        cudaFuncSetAttribute(k2_fused, cudaFuncAttributeMaxDynamicSharedMemorySize, SMEM_K2_BYTES);
        attr_done = true;
    }

    k1_setup<<<64, 256>>>(conv_w, start_t, end_t, trans);
    k2_fused<<<M_/128, 256, SMEM_K2_BYTES>>>(emb, conv_b);
    int nwarp = (NREC + 2)/3;
    int nthr  = nwarp*32;
    k4_chunks<<<(nthr + 127)/128, 128>>>(mask);
    k5_combine<<<1, 1024>>>(mask, labels, (float*)d_out);
}